// round 2
// baseline (speedup 1.0000x reference)
#include <cuda_runtime.h>

#define NFEAT 6272
#define MMEM  50000
#define MPAD  50048
#define CDIM  1024
#define BIMG  8
#define FHW   28
#define IMG   224
#define NPIX  (BIMG*IMG*IMG)

__device__ float g_f2[NFEAT];
__device__ float g_m2[MPAD];
__device__ unsigned int g_minbits[NFEAT];
__device__ float g_gauss[17];
__device__ float g_resized[NPIX];
__device__ float g_tmpb[NPIX];

typedef unsigned long long u64;

__device__ __forceinline__ u64 pk2(float lo, float hi){
    u64 r; asm("mov.b64 %0,{%1,%2};" : "=l"(r) : "f"(lo), "f"(hi)); return r;
}
__device__ __forceinline__ void upk2(u64 v, float &lo, float &hi){
    asm("mov.b64 {%0,%1},%2;" : "=f"(lo), "=f"(hi) : "l"(v));
}
__device__ __forceinline__ void fma2(u64 &d, u64 a, u64 b){
    asm("fma.rn.f32x2 %0,%1,%2,%0;" : "+l"(d) : "l"(a), "l"(b));
}

// ---------------------------------------------------------------------------
// init: reset per-feature min (FLT_MAX bits) + gaussian weights
// ---------------------------------------------------------------------------
__global__ void k_init(){
    int tid = blockIdx.x * blockDim.x + threadIdx.x;
    if (tid < NFEAT) g_minbits[tid] = 0x7F7FFFFFu;
    if (tid < 17){
        float s = 0.f;
        #pragma unroll
        for (int t = 0; t < 17; t++){ float d = (float)t - 8.f; s += expf(-(d*d)/32.f); }
        float d = (float)tid - 8.f;
        g_gauss[tid] = expf(-(d*d)/32.f) / s;
    }
}

// ---------------------------------------------------------------------------
// row squared norms; one warp per row. mode 0 -> g_f2, mode 1 -> g_m2.
// rows >= nvalid (memory pad rows) get +INF so the GEMM epilogue needs no mask.
// ---------------------------------------------------------------------------
__global__ void k_rownorm(const float* __restrict__ X, int nrows, int nvalid, int mode){
    int warp = (blockIdx.x * blockDim.x + threadIdx.x) >> 5;
    int lane = threadIdx.x & 31;
    if (warp >= nrows) return;
    float s;
    if (warp < nvalid){
        s = 0.f;
        const float4* p = (const float4*)(X + (size_t)warp * CDIM);
        #pragma unroll 4
        for (int i = lane; i < CDIM/4; i += 32){
            float4 v = p[i];
            s += v.x*v.x + v.y*v.y + v.z*v.z + v.w*v.w;
        }
    } else {
        s = __int_as_float(0x7F800000);
    }
    #pragma unroll
    for (int o = 16; o > 0; o >>= 1) s += __shfl_xor_sync(0xFFFFFFFFu, s, o);
    if (lane == 0){ if (mode == 0) g_f2[warp] = s; else g_m2[warp] = s; }
}

// ---------------------------------------------------------------------------
// fused distance GEMM + min epilogue.
// CTA tile 128(features) x 128(memory), K-chunk 8, double-buffered smem,
// per-thread 8x8 micro-tile via packed fma.rn.f32x2.
// ---------------------------------------------------------------------------
__global__ __launch_bounds__(256, 2)
void k_gemm_min(const float* __restrict__ A, const float* __restrict__ Bm){
    __shared__ float As[2][8][132];
    __shared__ float Bs[2][8][132];
    const int tid = threadIdx.x;
    const int tx = tid & 15, ty = tid >> 4;
    const int rowBase = blockIdx.y * 128;
    const int colBase = blockIdx.x * 128;

    const int lrow = tid >> 1;          // 0..127
    const int lk   = (tid & 1) * 4;     // 0 or 4
    const float* aptr = A + (size_t)(rowBase + lrow) * CDIM + lk;
    const int brow = colBase + lrow;
    const bool bval = brow < MMEM;
    const float* bptr = Bm + (size_t)(bval ? brow : 0) * CDIM + lk;

    u64 acc[8][4];
    #pragma unroll
    for (int r = 0; r < 8; r++)
        #pragma unroll
        for (int c = 0; c < 4; c++) acc[r][c] = 0ull;

    float4 av = *(const float4*)aptr;
    float4 bv = bval ? *(const float4*)bptr : make_float4(0.f,0.f,0.f,0.f);
    #pragma unroll
    for (int i = 0; i < 4; i++){
        As[0][lk+i][lrow] = ((const float*)&av)[i];
        Bs[0][lk+i][lrow] = ((const float*)&bv)[i];
    }
    __syncthreads();

    for (int ks = 0; ks < CDIM/8; ks++){
        const int cur = ks & 1;
        if (ks < CDIM/8 - 1){
            av = *(const float4*)(aptr + (ks+1)*8);
            bv = bval ? *(const float4*)(bptr + (ks+1)*8) : make_float4(0.f,0.f,0.f,0.f);
        }
        #pragma unroll
        for (int k = 0; k < 8; k++){
            float4 a0 = *(const float4*)&As[cur][k][ty*4];
            float4 a1 = *(const float4*)&As[cur][k][64 + ty*4];
            float4 b0 = *(const float4*)&Bs[cur][k][tx*4];
            float4 b1 = *(const float4*)&Bs[cur][k][64 + tx*4];
            u64 bp[4] = { pk2(b0.x,b0.y), pk2(b0.z,b0.w), pk2(b1.x,b1.y), pk2(b1.z,b1.w) };
            float af[8] = {a0.x,a0.y,a0.z,a0.w,a1.x,a1.y,a1.z,a1.w};
            #pragma unroll
            for (int r = 0; r < 8; r++){
                u64 ap = pk2(af[r], af[r]);
                #pragma unroll
                for (int c = 0; c < 4; c++) fma2(acc[r][c], ap, bp[c]);
            }
        }
        if (ks < CDIM/8 - 1){
            const int nxt = cur ^ 1;
            #pragma unroll
            for (int i = 0; i < 4; i++){
                As[nxt][lk+i][lrow] = ((const float*)&av)[i];
                Bs[nxt][lk+i][lrow] = ((const float*)&bv)[i];
            }
            __syncthreads();
        }
    }

    // epilogue: d2 = f2 + m2 - 2*dot ; min over this thread's cols, then across
    // the 16 threads (same ty) via shfl, then global atomicMin (float-as-uint).
    #pragma unroll
    for (int r = 0; r < 8; r++){
        int grow = rowBase + ((r < 4) ? (ty*4 + r) : (64 + ty*4 + r - 4));
        float f2v = g_f2[grow];
        float best = __int_as_float(0x7F800000);
        #pragma unroll
        for (int cp = 0; cp < 4; cp++){
            float lo, hi; upk2(acc[r][cp], lo, hi);
            int c = (cp < 2) ? (tx*4 + cp*2) : (64 + tx*4 + (cp-2)*2);
            int j = colBase + c;
            float d0 = f2v + g_m2[j]   - 2.f*lo;
            float d1 = f2v + g_m2[j+1] - 2.f*hi;
            best = fminf(best, fminf(d0, d1));
        }
        #pragma unroll
        for (int o = 1; o < 16; o <<= 1)
            best = fminf(best, __shfl_xor_sync(0xFFFFFFFFu, best, o));
        if (tx == 0)
            atomicMin(&g_minbits[grow], __float_as_uint(fmaxf(best, 0.f)));
    }
}

// ---------------------------------------------------------------------------
// per-image max -> sqrt -> out[0..7]
// ---------------------------------------------------------------------------
__global__ void k_scores(float* __restrict__ out){
    __shared__ unsigned int red[256];
    const int b = blockIdx.x;
    unsigned int mb = 0u;
    for (int i = threadIdx.x; i < FHW*FHW; i += 256)
        mb = max(mb, g_minbits[b*FHW*FHW + i]);
    red[threadIdx.x] = mb; __syncthreads();
    for (int s = 128; s > 0; s >>= 1){
        if (threadIdx.x < s) red[threadIdx.x] = max(red[threadIdx.x], red[threadIdx.x + s]);
        __syncthreads();
    }
    if (threadIdx.x == 0) out[b] = sqrtf(__uint_as_float(red[0]));
}

// ---------------------------------------------------------------------------
// bilinear 28 -> 224, half-pixel centers, edge clamp (== jax linear resize)
// ---------------------------------------------------------------------------
__global__ void k_resize(){
    int idx = blockIdx.x * blockDim.x + threadIdx.x;
    if (idx >= NPIX) return;
    int x = idx % IMG, y = (idx / IMG) % IMG, b = idx / (IMG*IMG);
    float fy = y * 0.125f - 0.4375f;
    float fx = x * 0.125f - 0.4375f;
    float fy0 = floorf(fy), fx0 = floorf(fx);
    float wy = fy - fy0, wx = fx - fx0;
    int y0 = max((int)fy0, 0), y1 = min((int)fy0 + 1, FHW-1);
    int x0 = max((int)fx0, 0), x1 = min((int)fx0 + 1, FHW-1);
    const unsigned int* mb = g_minbits + b*FHW*FHW;
    float s00 = sqrtf(__uint_as_float(mb[y0*FHW + x0]));
    float s01 = sqrtf(__uint_as_float(mb[y0*FHW + x1]));
    float s10 = sqrtf(__uint_as_float(mb[y1*FHW + x0]));
    float s11 = sqrtf(__uint_as_float(mb[y1*FHW + x1]));
    g_resized[idx] = (1.f-wy)*((1.f-wx)*s00 + wx*s01) + wy*((1.f-wx)*s10 + wx*s11);
}

// ---------------------------------------------------------------------------
// separable 17-tap gaussian blur with reflect indexing (pad=8, excl. edge)
// ---------------------------------------------------------------------------
__global__ void k_blurh(){
    __shared__ float w[17];
    if (threadIdx.x < 17) w[threadIdx.x] = g_gauss[threadIdx.x];
    __syncthreads();
    int idx = blockIdx.x * blockDim.x + threadIdx.x;
    if (idx >= NPIX) return;
    int x = idx % IMG, y = (idx / IMG) % IMG, b = idx / (IMG*IMG);
    const float* img = g_resized + b*IMG*IMG;
    float s = 0.f;
    #pragma unroll
    for (int t = 0; t < 17; t++){
        int yy = y - 8 + t;
        yy = (yy < 0) ? -yy : yy;
        yy = (yy > IMG-1) ? 2*(IMG-1) - yy : yy;
        s += w[t] * img[yy*IMG + x];
    }
    g_tmpb[idx] = s;
}

__global__ void k_blurv(float* __restrict__ out){
    __shared__ float w[17];
    if (threadIdx.x < 17) w[threadIdx.x] = g_gauss[threadIdx.x];
    __syncthreads();
    int idx = blockIdx.x * blockDim.x + threadIdx.x;
    if (idx >= NPIX) return;
    int x = idx % IMG, y = (idx / IMG) % IMG, b = idx / (IMG*IMG);
    const float* img = g_tmpb + b*IMG*IMG;
    float s = 0.f;
    #pragma unroll
    for (int t = 0; t < 17; t++){
        int xx = x - 8 + t;
        xx = (xx < 0) ? -xx : xx;
        xx = (xx > IMG-1) ? 2*(IMG-1) - xx : xx;
        s += w[t] * img[y*IMG + xx];
    }
    out[BIMG + idx] = s;   // masks start after the 8 image scores
}

// ---------------------------------------------------------------------------
extern "C" void kernel_launch(void* const* d_in, const int* in_sizes, int n_in,
                              void* d_out, int out_size){
    const float* feat = (const float*)d_in[0];
    const float* mem  = (const float*)d_in[1];
    if (n_in >= 2 && in_sizes[0] == MMEM * CDIM){  // defensive: identify by size
        const float* t = feat; feat = mem; mem = t;
    }
    float* out = (float*)d_out;

    k_init<<<(NFEAT + 255)/256, 256>>>();
    k_rownorm<<<(NFEAT*32)/256, 256>>>(feat, NFEAT, NFEAT, 0);
    k_rownorm<<<(MPAD*32)/256, 256>>>(mem, MPAD, MMEM, 1);

    dim3 g(MPAD/128, NFEAT/128);   // 391 x 49
    k_gemm_min<<<g, 256>>>(feat, mem);

    k_scores<<<BIMG, 256>>>(out);
    int pb = (NPIX + 255)/256;
    k_resize<<<pb, 256>>>();
    k_blurh<<<pb, 256>>>();
    k_blurv<<<pb, 256>>>(out);
}

// round 4
// speedup vs baseline: 5.7294x; 5.7294x over previous
#include <cuda_runtime.h>
#include <cuda_bf16.h>
#include <cstdint>

#define NFEAT 6272
#define MMEM  50000
#define CDIM  1024
#define BIMG  8
#define FHW   28
#define IMG   224
#define NPIX  (BIMG*IMG*IMG)

#define MTILE 128
#define NTILE 128
#define NTILES 391
#define MPAD2 (NTILES*NTILE)     // 50048
#define KCH   32                 // bf16 elems per K chunk
#define NCHUNKS (CDIM/KCH)       // 32
#define NSTAGE 4

// smem: 80-byte padded rows (32 bf16 data + 8 pad) -> conflict-free ldmatrix
#define ROWB   80
#define STAGEB (MTILE*ROWB)      // 10240 per operand
#define SA_OFF(st) ((st)*STAGEB)
#define SB_OFF(st) (NSTAGE*STAGEB + (st)*STAGEB)
#define AUX_OFF    (2*NSTAGE*STAGEB)        // 81920
#define SMEM_TOTAL (AUX_OFF + 512*3)        // m2s, f2s, sred

// ---- static device scratch ----
__device__ float g_f2[NFEAT];
__device__ float g_m2[MPAD2];
__device__ unsigned int g_minbits[NFEAT];
__device__ float g_gauss[17];
__device__ float g_resized[NPIX];
__device__ float g_tmpb[NPIX];
__device__ __nv_bfloat16 g_featb[NFEAT*CDIM];
__device__ __nv_bfloat16 g_memb[(size_t)MPAD2*CDIM];

static __device__ __forceinline__ uint32_t smem_u32(const void* p){
    uint32_t a; asm("{ .reg .u64 t; cvta.to.shared.u64 t, %1; cvt.u32.u64 %0, t; }"
                    : "=r"(a) : "l"(p));
    return a;
}
static __device__ __forceinline__ void cp16(uint32_t dst, const void* src){
    asm volatile("cp.async.cg.shared.global [%0], [%1], 16;" :: "r"(dst), "l"(src) : "memory");
}
static __device__ __forceinline__ void ldsm4(uint32_t p, uint32_t &r0, uint32_t &r1,
                                             uint32_t &r2, uint32_t &r3){
    asm volatile("ldmatrix.sync.aligned.m8n8.x4.shared.b16 {%0,%1,%2,%3}, [%4];"
                 : "=r"(r0), "=r"(r1), "=r"(r2), "=r"(r3) : "r"(p));
}
static __device__ __forceinline__ void mma16816(float* c, uint32_t a0, uint32_t a1,
                                                uint32_t a2, uint32_t a3,
                                                uint32_t b0, uint32_t b1){
    asm volatile("mma.sync.aligned.m16n8k16.row.col.f32.bf16.bf16.f32 "
                 "{%0,%1,%2,%3},{%4,%5,%6,%7},{%8,%9},{%0,%1,%2,%3};"
                 : "+f"(c[0]), "+f"(c[1]), "+f"(c[2]), "+f"(c[3])
                 : "r"(a0), "r"(a1), "r"(a2), "r"(a3), "r"(b0), "r"(b1));
}

// ---------------------------------------------------------------------------
__global__ void k_init(){
    int tid = blockIdx.x * blockDim.x + threadIdx.x;
    if (tid < NFEAT) g_minbits[tid] = 0x7F7FFFFFu;
    if (tid < 17){
        float s = 0.f;
        #pragma unroll
        for (int t = 0; t < 17; t++){ float d = (float)t - 8.f; s += expf(-(d*d)/32.f); }
        float d = (float)tid - 8.f;
        g_gauss[tid] = expf(-(d*d)/32.f) / s;
    }
}

// ---------------------------------------------------------------------------
// fused fp32->bf16 conversion + squared row norm. one warp per row.
// ---------------------------------------------------------------------------
__global__ void k_prep(const float* __restrict__ X, int nrows, int nvalid, int mode){
    int warp = (blockIdx.x * blockDim.x + threadIdx.x) >> 5;
    int lane = threadIdx.x & 31;
    if (warp >= nrows) return;
    __nv_bfloat16* dst = (mode == 0 ? g_featb : g_memb) + (size_t)warp * CDIM;
    if (warp >= nvalid){
        uint2 z = make_uint2(0u, 0u);
        #pragma unroll
        for (int j = 0; j < 8; j++) ((uint2*)dst)[j*32 + lane] = z;
        if (lane == 0) g_m2[warp] = __int_as_float(0x7F800000);
        return;
    }
    const float4* src = (const float4*)(X + (size_t)warp * CDIM);
    float s = 0.f;
    #pragma unroll
    for (int j = 0; j < 8; j++){
        float4 v = src[j*32 + lane];
        s += v.x*v.x + v.y*v.y + v.z*v.z + v.w*v.w;
        __nv_bfloat162 p0 = __floats2bfloat162_rn(v.x, v.y);
        __nv_bfloat162 p1 = __floats2bfloat162_rn(v.z, v.w);
        uint2 o; o.x = *(uint32_t*)&p0; o.y = *(uint32_t*)&p1;
        ((uint2*)dst)[j*32 + lane] = o;
    }
    #pragma unroll
    for (int o = 16; o > 0; o >>= 1) s += __shfl_xor_sync(0xFFFFFFFFu, s, o);
    if (lane == 0){ if (mode == 0) g_f2[warp] = s; else g_m2[warp] = s; }
}

// ---------------------------------------------------------------------------
// bf16 HMMA distance GEMM + min epilogue.
// CTA 128x128, 8 warps (2M x 4N), warp tile 64x32, 4-stage cp.async pipeline.
// ---------------------------------------------------------------------------
__global__ __launch_bounds__(256, 2)
void k_gemm_tc(){
    extern __shared__ char smraw[];
    const uint32_t sbase = smem_u32(smraw);
    const int tid = threadIdx.x;
    const int wid = tid >> 5, lane = tid & 31;
    const int warpM = wid >> 2, warpN = wid & 3;
    const int rowBase = blockIdx.x * MTILE;
    const int colBase = blockIdx.y * NTILE;

    float* m2s = (float*)(smraw + AUX_OFF);
    float* f2s = (float*)(smraw + AUX_OFF + 512);
    unsigned int* sred = (unsigned int*)(smraw + AUX_OFF + 1024);
    if (tid < 128){
        m2s[tid] = g_m2[colBase + tid];
        f2s[tid] = g_f2[rowBase + tid];
        sred[tid] = 0x7F7FFFFFu;
    }

    const char* aG = (const char*)g_featb + (size_t)rowBase * (CDIM*2);
    const char* bG = (const char*)g_memb  + (size_t)colBase * (CDIM*2);

    // per-thread cp.async assignment: 4 x 16B per stage
    const int ci = tid;                 // 0..255 -> A rows; +256..511 -> B
    // issue lambda-ish macro
    #define ISSUE_STAGE(ks, st) do { \
        _Pragma("unroll") \
        for (int t = 0; t < 4; t++){ \
            int i = ci + t * 256; \
            if (i < 512){ \
                int row = i >> 2, g = i & 3; \
                cp16(sbase + SA_OFF(st) + row*ROWB + g*16, \
                     aG + (size_t)row*(CDIM*2) + (ks)*(KCH*2) + g*16); \
            } else { \
                int j = i - 512; int row = j >> 2, g = j & 3; \
                cp16(sbase + SB_OFF(st) + row*ROWB + g*16, \
                     bG + (size_t)row*(CDIM*2) + (ks)*(KCH*2) + g*16); \
            } \
        } \
        asm volatile("cp.async.commit_group;" ::: "memory"); \
    } while(0)

    // prologue: stages 0..2
    ISSUE_STAGE(0, 0);
    ISSUE_STAGE(1, 1);
    ISSUE_STAGE(2, 2);

    float acc[4][4][4];
    #pragma unroll
    for (int mi = 0; mi < 4; mi++)
        #pragma unroll
        for (int ni = 0; ni < 4; ni++)
            #pragma unroll
            for (int k = 0; k < 4; k++) acc[mi][ni][k] = 0.f;

    const int lrow = lane & 15;
    const int lcol16 = (lane >> 4) & 1;

    for (int ks = 0; ks < NCHUNKS; ks++){
        asm volatile("cp.async.wait_group 2;" ::: "memory");
        __syncthreads();

        // issue next (empty commit keeps group accounting uniform)
        if (ks + 3 < NCHUNKS){ ISSUE_STAGE(ks + 3, (ks + 3) & 3); }
        else { asm volatile("cp.async.commit_group;" ::: "memory"); }

        const uint32_t sa = sbase + SA_OFF(ks & 3);
        const uint32_t sb = sbase + SB_OFF(ks & 3);

        #pragma unroll
        for (int k2 = 0; k2 < 2; k2++){
            uint32_t fa[4][4], fb[2][4];
            #pragma unroll
            for (int mi = 0; mi < 4; mi++){
                uint32_t p = sa + (warpM*64 + mi*16 + lrow)*ROWB + k2*32 + lcol16*16;
                ldsm4(p, fa[mi][0], fa[mi][1], fa[mi][2], fa[mi][3]);
            }
            #pragma unroll
            for (int nh = 0; nh < 2; nh++){
                uint32_t p = sb + (warpN*32 + nh*16 + lrow)*ROWB + k2*32 + lcol16*16;
                ldsm4(p, fb[nh][0], fb[nh][1], fb[nh][2], fb[nh][3]);
            }
            #pragma unroll
            for (int mi = 0; mi < 4; mi++)
                #pragma unroll
                for (int ni = 0; ni < 4; ni++){
                    int nh = ni >> 1, od = ni & 1;
                    mma16816(acc[mi][ni], fa[mi][0], fa[mi][1], fa[mi][2], fa[mi][3],
                             fb[nh][od], fb[nh][od + 2]);
                }
        }
    }
    #undef ISSUE_STAGE

    // ---- epilogue: d2 = f2 + m2 - 2*dot, min-reduce ----
    {
        const int q = lane >> 2;        // row-in-8 group
        const int ql = lane & 3;        // col pair selector
        float m2v[4][2], f2lo[4], f2hi[4];
        #pragma unroll
        for (int ni = 0; ni < 4; ni++){
            int c = warpN*32 + ni*8 + 2*ql;
            m2v[ni][0] = m2s[c];
            m2v[ni][1] = m2s[c + 1];
        }
        #pragma unroll
        for (int mi = 0; mi < 4; mi++){
            f2lo[mi] = f2s[warpM*64 + mi*16 + q];
            f2hi[mi] = f2s[warpM*64 + mi*16 + q + 8];
        }
        #pragma unroll
        for (int mi = 0; mi < 4; mi++){
            float vlo = __int_as_float(0x7F800000);
            float vhi = vlo;
            #pragma unroll
            for (int ni = 0; ni < 4; ni++){
                vlo = fminf(vlo, fminf(fmaf(-2.f, acc[mi][ni][0], f2lo[mi] + m2v[ni][0]),
                                       fmaf(-2.f, acc[mi][ni][1], f2lo[mi] + m2v[ni][1])));
                vhi = fminf(vhi, fminf(fmaf(-2.f, acc[mi][ni][2], f2hi[mi] + m2v[ni][0]),
                                       fmaf(-2.f, acc[mi][ni][3], f2hi[mi] + m2v[ni][1])));
            }
            // quad reduce (lanes sharing q)
            #pragma unroll
            for (int o = 1; o < 4; o <<= 1){
                vlo = fminf(vlo, __shfl_xor_sync(0xFFFFFFFFu, vlo, o));
                vhi = fminf(vhi, __shfl_xor_sync(0xFFFFFFFFu, vhi, o));
            }
            if (ql == 0){
                int r = warpM*64 + mi*16 + q;
                atomicMin(&sred[r],     __float_as_uint(fmaxf(vlo, 0.f)));
                atomicMin(&sred[r + 8], __float_as_uint(fmaxf(vhi, 0.f)));
            }
        }
    }
    __syncthreads();
    if (tid < 128)
        atomicMin(&g_minbits[rowBase + tid], sred[tid]);
}

// ---------------------------------------------------------------------------
__global__ void k_scores(float* __restrict__ out){
    __shared__ unsigned int red[256];
    const int b = blockIdx.x;
    unsigned int mb = 0u;
    for (int i = threadIdx.x; i < FHW*FHW; i += 256)
        mb = max(mb, g_minbits[b*FHW*FHW + i]);
    red[threadIdx.x] = mb; __syncthreads();
    for (int s = 128; s > 0; s >>= 1){
        if (threadIdx.x < s) red[threadIdx.x] = max(red[threadIdx.x], red[threadIdx.x + s]);
        __syncthreads();
    }
    if (threadIdx.x == 0) out[b] = sqrtf(__uint_as_float(red[0]));
}

__global__ void k_resize(){
    int idx = blockIdx.x * blockDim.x + threadIdx.x;
    if (idx >= NPIX) return;
    int x = idx % IMG, y = (idx / IMG) % IMG, b = idx / (IMG*IMG);
    float fy = y * 0.125f - 0.4375f;
    float fx = x * 0.125f - 0.4375f;
    float fy0 = floorf(fy), fx0 = floorf(fx);
    float wy = fy - fy0, wx = fx - fx0;
    int y0 = max((int)fy0, 0), y1 = min((int)fy0 + 1, FHW-1);
    int x0 = max((int)fx0, 0), x1 = min((int)fx0 + 1, FHW-1);
    const unsigned int* mb = g_minbits + b*FHW*FHW;
    float s00 = sqrtf(__uint_as_float(mb[y0*FHW + x0]));
    float s01 = sqrtf(__uint_as_float(mb[y0*FHW + x1]));
    float s10 = sqrtf(__uint_as_float(mb[y1*FHW + x0]));
    float s11 = sqrtf(__uint_as_float(mb[y1*FHW + x1]));
    g_resized[idx] = (1.f-wy)*((1.f-wx)*s00 + wx*s01) + wy*((1.f-wx)*s10 + wx*s11);
}

__global__ void k_blurh(){
    __shared__ float w[17];
    if (threadIdx.x < 17) w[threadIdx.x] = g_gauss[threadIdx.x];
    __syncthreads();
    int idx = blockIdx.x * blockDim.x + threadIdx.x;
    if (idx >= NPIX) return;
    int x = idx % IMG, y = (idx / IMG) % IMG, b = idx / (IMG*IMG);
    const float* img = g_resized + b*IMG*IMG;
    float s = 0.f;
    #pragma unroll
    for (int t = 0; t < 17; t++){
        int yy = y - 8 + t;
        yy = (yy < 0) ? -yy : yy;
        yy = (yy > IMG-1) ? 2*(IMG-1) - yy : yy;
        s += w[t] * img[yy*IMG + x];
    }
    g_tmpb[idx] = s;
}

__global__ void k_blurv(float* __restrict__ out){
    __shared__ float w[17];
    if (threadIdx.x < 17) w[threadIdx.x] = g_gauss[threadIdx.x];
    __syncthreads();
    int idx = blockIdx.x * blockDim.x + threadIdx.x;
    if (idx >= NPIX) return;
    int x = idx % IMG, y = (idx / IMG) % IMG, b = idx / (IMG*IMG);
    const float* img = g_tmpb + b*IMG*IMG;
    float s = 0.f;
    #pragma unroll
    for (int t = 0; t < 17; t++){
        int xx = x - 8 + t;
        xx = (xx < 0) ? -xx : xx;
        xx = (xx > IMG-1) ? 2*(IMG-1) - xx : xx;
        s += w[t] * img[y*IMG + xx];
    }
    out[BIMG + idx] = s;
}

// ---------------------------------------------------------------------------
extern "C" void kernel_launch(void* const* d_in, const int* in_sizes, int n_in,
                              void* d_out, int out_size){
    const float* feat = (const float*)d_in[0];
    const float* mem  = (const float*)d_in[1];
    if (n_in >= 2 && in_sizes[0] == MMEM * CDIM){
        const float* t = feat; feat = mem; mem = t;
    }
    float* out = (float*)d_out;

    cudaFuncSetAttribute(k_gemm_tc, cudaFuncAttributeMaxDynamicSharedMemorySize, SMEM_TOTAL);

    k_init<<<(NFEAT + 255)/256, 256>>>();
    k_prep<<<NFEAT/8, 256>>>(feat, NFEAT, NFEAT, 0);
    k_prep<<<MPAD2/8, 256>>>(mem, MPAD2, MMEM, 1);

    dim3 g(NFEAT/MTILE, NTILES);   // 49 x 391, x fastest -> B tile L2 reuse
    k_gemm_tc<<<g, 256, SMEM_TOTAL>>>();

    k_scores<<<BIMG, 256>>>(out);
    int pb = (NPIX + 255)/256;
    k_resize<<<pb, 256>>>();
    k_blurh<<<pb, 256>>>();
    k_blurv<<<pb, 256>>>(out);
}